// round 4
// baseline (speedup 1.0000x reference)
#include <cuda_runtime.h>

// ContrastiveLoss fused implementation.
// loss = -(1/B^2) * sum_j w_j * S_j
//   S_j = sum_k logits[j,k] - B*max_j - B*log(sum_k exp(logits[j,k]-max_j))
//   logits = u @ A^T,  u[j] = A[j]/T + (A[j] @ Cov[label_j]) / (2 T^3)
//   w_j = m_j / (m_j + eps), m_j = count of rows sharing label_j

#define BN 4096
#define DD 128
#define CN 100
#define NSPLIT 8
#define TK 16

__device__ float  g_u[BN * DD];
__device__ float  g_pmax[NSPLIT * BN];
__device__ float  g_pse[NSPLIT * BN];
__device__ float  g_psl[NSPLIT * BN];
__device__ int    g_cnt[CN];
__device__ int    g_is64;
__device__ double g_acc;

// Label fetch robust to int32-vs-int64 on-device layout.
__device__ __forceinline__ int get_label(const void* L, int t) {
    int v;
    if (g_is64) v = (int)((const long long*)L)[t];
    else        v = ((const int*)L)[t];
    // clamp defensively; no-op for valid labels
    return min(max(v, 0), CN - 1);
}

// ---------------------------------------------------------------------------
// Detect labels dtype: if int64, every odd int32 word is a zero high-word.
__global__ void k_detect(const int* __restrict__ Lw) {
    int t = threadIdx.x;                  // 64 threads, words 0..63
    int odd_nonzero = ((t & 1) && Lw[t] != 0) ? 1 : 0;
    unsigned any = __ballot_sync(0xffffffffu, odd_nonzero);
    __shared__ unsigned s[2];
    s[t >> 5] = any;                       // both warps write their ballot
    __syncthreads();
    if (t == 0) g_is64 = ((s[0] | s[1]) == 0u) ? 1 : 0;
}

__global__ void k_init() {
    int t = threadIdx.x;
    if (t < CN) g_cnt[t] = 0;
    if (t == 0) g_acc = 0.0;
}

__global__ void k_hist(const void* __restrict__ labels) {
    int t = blockIdx.x * blockDim.x + threadIdx.x;
    if (t < BN) atomicAdd(&g_cnt[get_label(labels, t)], 1);
}

// ---------------------------------------------------------------------------
// u[j,e] = A[j,e]/T + (sum_d A[j,d] * Cov[l_j][d,e]) / (2 T^3)
// one block per row, 128 threads (thread = output column e)
__global__ void k_u(const float* __restrict__ A,
                    const void* __restrict__ labels,
                    const float* __restrict__ Cov) {
    int row = blockIdx.x;
    int e = threadIdx.x;
    __shared__ float As[DD];
    float a_e = A[row * DD + e];
    As[e] = a_e;
    __syncthreads();
    const float* Cr = Cov + (long)get_label(labels, row) * (DD * DD);
    float acc = 0.f;
#pragma unroll 8
    for (int d = 0; d < DD; d++)
        acc = fmaf(As[d], Cr[d * DD + e], acc);
    const float invT = (float)(1.0 / 0.07);
    const float s2   = (float)(1.0 / (2.0 * 0.07 * 0.07 * 0.07));
    g_u[row * DD + e] = a_e * invT + acc * s2;
}

// ---------------------------------------------------------------------------
// Fused GEMM (u @ A^T) + online per-row softmax statistics.
// Block tile 128 rows x 128 cols, 256 threads, 8x8 microtile.
// Grid: (BN/128, NSPLIT). Each block covers 512 columns (4 tiles of 128)
// and writes per-row partial (max, sumexp, sumlogits) for its column split.
__global__ __launch_bounds__(256, 2)
void k_gemm(const float* __restrict__ Af) {
    __shared__ float us[TK][132];
    __shared__ float vs[TK][132];
    const int tid = threadIdx.x;
    const int tx = tid & 15;
    const int ty = tid >> 4;
    const int row0 = blockIdx.x * 128;
    const int colbase = blockIdx.y * (BN / NSPLIT);

    float M[8], L[8], S[8];
#pragma unroll
    for (int i = 0; i < 8; i++) { M[i] = -3.0e38f; L[i] = 0.f; S[i] = 0.f; }

    for (int ct = 0; ct < (BN / NSPLIT) / 128; ct++) {
        const int col0 = colbase + ct * 128;
        float acc[8][8];
#pragma unroll
        for (int i = 0; i < 8; i++)
#pragma unroll
            for (int j = 0; j < 8; j++) acc[i][j] = 0.f;

        for (int k0 = 0; k0 < DD; k0 += TK) {
            __syncthreads();
#pragma unroll
            for (int r = 0; r < 2; r++) {
                int idx = tid + r * 256;       // 0..511 float4 slots
                int m = idx >> 2;              // 0..127 (tile row)
                int kq = (idx & 3) << 2;       // 0,4,8,12 (k offset)
                float4 fu = *(const float4*)(g_u + (row0 + m) * DD + k0 + kq);
                us[kq + 0][m] = fu.x; us[kq + 1][m] = fu.y;
                us[kq + 2][m] = fu.z; us[kq + 3][m] = fu.w;
                float4 fa = *(const float4*)(Af + (col0 + m) * DD + k0 + kq);
                vs[kq + 0][m] = fa.x; vs[kq + 1][m] = fa.y;
                vs[kq + 2][m] = fa.z; vs[kq + 3][m] = fa.w;
            }
            __syncthreads();
#pragma unroll
            for (int k = 0; k < TK; k++) {
                float uf[8], af[8];
                *(float4*)&uf[0] = *(const float4*)&us[k][ty * 4];
                *(float4*)&uf[4] = *(const float4*)&us[k][64 + ty * 4];
                *(float4*)&af[0] = *(const float4*)&vs[k][tx * 4];
                *(float4*)&af[4] = *(const float4*)&vs[k][64 + tx * 4];
#pragma unroll
                for (int i = 0; i < 8; i++)
#pragma unroll
                    for (int j = 0; j < 8; j++)
                        acc[i][j] = fmaf(uf[i], af[j], acc[i][j]);
            }
        }

        // Online softmax update; 16 lanes (same ty) share each row.
#pragma unroll
        for (int i = 0; i < 8; i++) {
            float tmax = acc[i][0];
#pragma unroll
            for (int j = 1; j < 8; j++) tmax = fmaxf(tmax, acc[i][j]);
#pragma unroll
            for (int o = 8; o >= 1; o >>= 1)
                tmax = fmaxf(tmax, __shfl_xor_sync(0xffffffffu, tmax, o));
            float nm = fmaxf(M[i], tmax);
            float se = 0.f, sl = 0.f;
#pragma unroll
            for (int j = 0; j < 8; j++) {
                se += __expf(acc[i][j] - nm);
                sl += acc[i][j];
            }
#pragma unroll
            for (int o = 8; o >= 1; o >>= 1) {
                se += __shfl_xor_sync(0xffffffffu, se, o);
                sl += __shfl_xor_sync(0xffffffffu, sl, o);
            }
            L[i] = L[i] * __expf(M[i] - nm) + se;
            S[i] += sl;
            M[i] = nm;
        }
    }

    if (tx == 0) {
#pragma unroll
        for (int i = 0; i < 8; i++) {
            int lr = (i < 4) ? (ty * 4 + i) : (64 + ty * 4 + (i - 4));
            int o = blockIdx.y * BN + row0 + lr;
            g_pmax[o] = M[i];
            g_pse[o]  = L[i];
            g_psl[o]  = S[i];
        }
    }
}

// ---------------------------------------------------------------------------
// Combine the NSPLIT partials per row, weight, reduce, accumulate in double.
__global__ void k_combine(const void* __restrict__ labels) {
    int j = blockIdx.x * blockDim.x + threadIdx.x;  // 16 x 256 = 4096
    float M = -3.0e38f;
#pragma unroll
    for (int s = 0; s < NSPLIT; s++) M = fmaxf(M, g_pmax[s * BN + j]);
    float L = 0.f, Ssum = 0.f;
#pragma unroll
    for (int s = 0; s < NSPLIT; s++) {
        L += g_pse[s * BN + j] * __expf(g_pmax[s * BN + j] - M);
        Ssum += g_psl[s * BN + j];
    }
    float Sj = Ssum - (float)BN * M - (float)BN * logf(L + 1e-12f);
    float mc = (float)g_cnt[get_label(labels, j)];
    float w = mc / (mc + 1e-12f);
    double c = (double)(w * Sj);

#pragma unroll
    for (int o = 16; o >= 1; o >>= 1)
        c += __shfl_xor_sync(0xffffffffu, c, o);

    __shared__ double red[8];
    if ((threadIdx.x & 31) == 0) red[threadIdx.x >> 5] = c;
    __syncthreads();
    if (threadIdx.x < 8) {
        double v = red[threadIdx.x];
#pragma unroll
        for (int o = 4; o >= 1; o >>= 1)
            v += __shfl_xor_sync(0xffu, v, o);
        if (threadIdx.x == 0) atomicAdd(&g_acc, v);
    }
}

__global__ void k_final(float* out) {
    out[0] = (float)(-g_acc / ((double)BN * (double)BN));
}

// ---------------------------------------------------------------------------
extern "C" void kernel_launch(void* const* d_in, const int* in_sizes, int n_in,
                              void* d_out, int out_size) {
    const float* feats = (const float*)d_in[0];   // [4096,1,128] f32
    const void*  labels = d_in[1];                // [4096] i32 or i64 (detected)
    const float* cov   = (const float*)d_in[2];   // [100,128,128] f32
    float* out = (float*)d_out;

    k_detect<<<1, 64>>>((const int*)labels);
    k_init<<<1, 128>>>();
    k_hist<<<BN / 256, 256>>>(labels);
    k_u<<<BN, DD>>>(feats, labels, cov);
    dim3 grid(BN / 128, NSPLIT);
    k_gemm<<<grid, 256>>>(feats);
    k_combine<<<BN / 256, 256>>>(labels);
    k_final<<<1, 1>>>(out);
}

// round 7
// speedup vs baseline: 1.6957x; 1.6957x over previous
#include <cuda_runtime.h>
#include <cuda_bf16.h>
#include <cstdint>

// ContrastiveLoss: fused bf16-split HMMA GEMM + online softmax.
// loss = -(1/B^2) * sum_j w_j * S_j
//   S_j = sum_k logits[j,k] - B*max_j - B*log(sum_k exp(logits[j,k]-max_j)+eps)
//   logits = u @ A^T, u[j] = A[j]/T + (A[j] @ Cov[label_j]) / (2 T^3)
// fp32 GEMM emulated as bf16 hi/lo with 3 products (hi*hi + hi*lo + lo*hi),
// computed via mma.sync.m16n8k16 (legal under compute_103; tcgen05 is not).

#define BN 4096
#define DD 128
#define CN 100
#define NSPLIT 4
#define CTILES ((BN / NSPLIT) / 128)   // 8

__device__ __align__(16) __nv_bfloat16 g_uhi[BN * DD];
__device__ __align__(16) __nv_bfloat16 g_ulo[BN * DD];
__device__ __align__(16) __nv_bfloat16 g_ahi[BN * DD];
__device__ __align__(16) __nv_bfloat16 g_alo[BN * DD];
__device__ float  g_pmax[NSPLIT * BN];
__device__ float  g_pse[NSPLIT * BN];
__device__ float  g_psl[NSPLIT * BN];
__device__ int    g_cnt[CN];
__device__ int    g_is64;
__device__ double g_acc;

// ---------------------------------------------------------------- helpers
__device__ __forceinline__ uint32_t smem_u32(const void* p) {
    uint32_t a;
    asm("{ .reg .u64 t; cvta.to.shared.u64 t, %1; cvt.u32.u64 %0, t; }"
        : "=r"(a) : "l"(p));
    return a;
}

__device__ __forceinline__ void ldmx4(uint32_t* r, uint32_t addr) {
    asm volatile("ldmatrix.sync.aligned.m8n8.x4.shared.b16 {%0,%1,%2,%3}, [%4];"
                 : "=r"(r[0]), "=r"(r[1]), "=r"(r[2]), "=r"(r[3]) : "r"(addr));
}

__device__ __forceinline__ void mma_bf16(float* c, const uint32_t* a,
                                         uint32_t b0, uint32_t b1) {
    asm volatile(
        "mma.sync.aligned.m16n8k16.row.col.f32.bf16.bf16.f32 "
        "{%0,%1,%2,%3}, {%4,%5,%6,%7}, {%8,%9}, {%0,%1,%2,%3};"
        : "+f"(c[0]), "+f"(c[1]), "+f"(c[2]), "+f"(c[3])
        : "r"(a[0]), "r"(a[1]), "r"(a[2]), "r"(a[3]), "r"(b0), "r"(b1));
}

// ---------------------------------------------------------------- label utils
__device__ __forceinline__ int get_label(const void* L, int t) {
    int v;
    if (g_is64) v = (int)((const long long*)L)[t];
    else        v = ((const int*)L)[t];
    return min(max(v, 0), CN - 1);
}

__global__ void k_detect(const int* __restrict__ Lw) {
    int t = threadIdx.x;
    int odd_nonzero = ((t & 1) && Lw[t] != 0) ? 1 : 0;
    unsigned any = __ballot_sync(0xffffffffu, odd_nonzero);
    __shared__ unsigned s[2];
    s[t >> 5] = any;
    __syncthreads();
    if (t == 0) g_is64 = ((s[0] | s[1]) == 0u) ? 1 : 0;
}

__global__ void k_init() {
    int t = threadIdx.x;
    if (t < CN) g_cnt[t] = 0;
    if (t == 0) g_acc = 0.0;
}

__global__ void k_hist(const void* __restrict__ labels) {
    int t = blockIdx.x * blockDim.x + threadIdx.x;
    if (t < BN) atomicAdd(&g_cnt[get_label(labels, t)], 1);
}

__global__ void k_split(const float* __restrict__ A) {
    int i = blockIdx.x * blockDim.x + threadIdx.x;
    float x = A[i];
    __nv_bfloat16 h = __float2bfloat16(x);
    g_ahi[i] = h;
    g_alo[i] = __float2bfloat16(x - __bfloat162float(h));
}

// ---------------------------------------------------------------------------
__global__ void k_u(const float* __restrict__ A,
                    const void* __restrict__ labels,
                    const float* __restrict__ Cov) {
    int row = blockIdx.x;
    int e = threadIdx.x;
    __shared__ float As[DD];
    float a_e = A[row * DD + e];
    As[e] = a_e;
    __syncthreads();
    const float* Cr = Cov + (long)get_label(labels, row) * (DD * DD);
    float acc = 0.f;
#pragma unroll 8
    for (int d = 0; d < DD; d++)
        acc = fmaf(As[d], Cr[d * DD + e], acc);
    const float invT = (float)(1.0 / 0.07);
    const float s2   = (float)(1.0 / (2.0 * 0.07 * 0.07 * 0.07));
    float uv = a_e * invT + acc * s2;
    __nv_bfloat16 h = __float2bfloat16(uv);
    g_uhi[row * DD + e] = h;
    g_ulo[row * DD + e] = __float2bfloat16(uv - __bfloat162float(h));
}

// ---------------------------------------------------------------------------
// Fused HMMA GEMM + online softmax. Grid (BN/128, NSPLIT), 256 threads.
// smem tiles: 128 rows x 128 bf16, row stride 272 B (conflict-free ldmatrix).
#define SROW 272
#define TILE_B (128 * SROW)
#define OFF_UHI 0
#define OFF_ULO (TILE_B)
#define OFF_AHI (2 * TILE_B)
#define OFF_ALO (3 * TILE_B)
#define SMEM_BYTES (4 * TILE_B)

__global__ __launch_bounds__(256, 1)
void k_gemm_mma() {
    extern __shared__ char smem[];
    const uint32_t sb = smem_u32(smem);
    const int tid = threadIdx.x;
    const int wid = tid >> 5;
    const int lid = tid & 31;
    const int warp_m = wid & 3;          // 32-row slab
    const int warp_n = wid >> 2;         // 64-col slab
    const int row0 = blockIdx.x * 128;
    const int colbase = blockIdx.y * (BN / NSPLIT);

    // per-lane ldmatrix offsets (within a 16x16 frag at (fr0, kb)):
    const int rsel = (lid & 7) + ((lid >> 3) & 1) * 8;
    const int csel = ((lid >> 4) & 1) * 16;

    uint32_t aoff[2], boff[4];
#pragma unroll
    for (int mf = 0; mf < 2; mf++)
        aoff[mf] = (uint32_t)((warp_m * 32 + mf * 16 + rsel) * SROW + csel);
#pragma unroll
    for (int q = 0; q < 4; q++)
        boff[q] = (uint32_t)((warp_n * 64 + q * 16 + rsel) * SROW + csel);

    // load u tiles once
#pragma unroll
    for (int i = 0; i < 8; i++) {
        int idx = i * 256 + tid;          // 0..2047 uint4 slots
        int r = idx >> 4, c = idx & 15;
        char* dh = smem + OFF_UHI + r * SROW + c * 16;
        char* dl = smem + OFF_ULO + r * SROW + c * 16;
        *(uint4*)dh = *((const uint4*)(g_uhi + (size_t)(row0 + r) * DD) + c);
        *(uint4*)dl = *((const uint4*)(g_ulo + (size_t)(row0 + r) * DD) + c);
    }

    float M[4], L[4], S[4];
#pragma unroll
    for (int i = 0; i < 4; i++) { M[i] = -3.0e38f; L[i] = 0.f; S[i] = 0.f; }

    for (int ct = 0; ct < CTILES; ct++) {
        const int col0 = colbase + ct * 128;
        __syncthreads();   // protect A smem from previous iteration's readers
#pragma unroll
        for (int i = 0; i < 8; i++) {
            int idx = i * 256 + tid;
            int r = idx >> 4, c = idx & 15;
            char* dh = smem + OFF_AHI + r * SROW + c * 16;
            char* dl = smem + OFF_ALO + r * SROW + c * 16;
            *(uint4*)dh = *((const uint4*)(g_ahi + (size_t)(col0 + r) * DD) + c);
            *(uint4*)dl = *((const uint4*)(g_alo + (size_t)(col0 + r) * DD) + c);
        }
        __syncthreads();

        float acc[2][8][4];
#pragma unroll
        for (int mf = 0; mf < 2; mf++)
#pragma unroll
            for (int nf = 0; nf < 8; nf++)
#pragma unroll
                for (int c = 0; c < 4; c++) acc[mf][nf][c] = 0.f;

        // 3 passes: hi*hi, hi*lo, lo*hi
#pragma unroll
        for (int pass = 0; pass < 3; pass++) {
            const uint32_t abase = sb + (pass == 2 ? OFF_ULO : OFF_UHI);
            const uint32_t bbase = sb + (pass == 1 ? OFF_ALO : OFF_AHI);
#pragma unroll
            for (int ks = 0; ks < 8; ks++) {
                const uint32_t kb = ks * 32;
                uint32_t afr[2][4];
#pragma unroll
                for (int mf = 0; mf < 2; mf++)
                    ldmx4(afr[mf], abase + aoff[mf] + kb);
                uint32_t bfr[4][4];
#pragma unroll
                for (int q = 0; q < 4; q++)
                    ldmx4(bfr[q], bbase + boff[q] + kb);
#pragma unroll
                for (int mf = 0; mf < 2; mf++)
#pragma unroll
                    for (int q = 0; q < 4; q++) {
                        mma_bf16(acc[mf][2 * q],     afr[mf], bfr[q][0], bfr[q][2]);
                        mma_bf16(acc[mf][2 * q + 1], afr[mf], bfr[q][1], bfr[q][3]);
                    }
            }
        }

        // online softmax update: thread owns 4 rows x 16 cols
#pragma unroll
        for (int ri = 0; ri < 4; ri++) {
            const int mf = ri >> 1, rp = ri & 1;
            float vmax = -3.0e38f;
#pragma unroll
            for (int nf = 0; nf < 8; nf++) {
                vmax = fmaxf(vmax, acc[mf][nf][rp * 2]);
                vmax = fmaxf(vmax, acc[mf][nf][rp * 2 + 1]);
            }
            vmax = fmaxf(vmax, __shfl_xor_sync(0xffffffffu, vmax, 1));
            vmax = fmaxf(vmax, __shfl_xor_sync(0xffffffffu, vmax, 2));
            float nm = fmaxf(M[ri], vmax);
            float se = 0.f, sl = 0.f;
#pragma unroll
            for (int nf = 0; nf < 8; nf++) {
#pragma unroll
                for (int c = 0; c < 2; c++) {
                    float v = acc[mf][nf][rp * 2 + c];
                    se += __expf(v - nm);
                    sl += v;
                }
            }
            se += __shfl_xor_sync(0xffffffffu, se, 1);
            se += __shfl_xor_sync(0xffffffffu, se, 2);
            sl += __shfl_xor_sync(0xffffffffu, sl, 1);
            sl += __shfl_xor_sync(0xffffffffu, sl, 2);
            L[ri] = L[ri] * __expf(M[ri] - nm) + se;
            S[ri] += sl;
            M[ri] = nm;
        }
    }

    __syncthreads();   // all warps done with smem tiles; reuse as scratch
    float* msc = (float*)(smem + OFF_AHI);        // [2][128]
    float* lsc = msc + 256;
    float* ssc = msc + 512;
    if ((lid & 3) == 0) {
#pragma unroll
        for (int ri = 0; ri < 4; ri++) {
            int row = warp_m * 32 + (ri >> 1) * 16 + (ri & 1) * 8 + (lid >> 2);
            msc[warp_n * 128 + row] = M[ri];
            lsc[warp_n * 128 + row] = L[ri];
            ssc[warp_n * 128 + row] = S[ri];
        }
    }
    __syncthreads();
    if (tid < 128) {
        float m0 = msc[tid], m1 = msc[128 + tid];
        float nm = fmaxf(m0, m1);
        float Lm = lsc[tid] * __expf(m0 - nm) + lsc[128 + tid] * __expf(m1 - nm);
        int o = blockIdx.y * BN + row0 + tid;
        g_pmax[o] = nm;
        g_pse[o]  = Lm;
        g_psl[o]  = ssc[tid] + ssc[128 + tid];
    }
}

// ---------------------------------------------------------------------------
__global__ void k_combine(const void* __restrict__ labels) {
    int j = blockIdx.x * blockDim.x + threadIdx.x;
    float M = -3.0e38f;
#pragma unroll
    for (int s = 0; s < NSPLIT; s++) M = fmaxf(M, g_pmax[s * BN + j]);
    float L = 0.f, Ssum = 0.f;
#pragma unroll
    for (int s = 0; s < NSPLIT; s++) {
        L += g_pse[s * BN + j] * __expf(g_pmax[s * BN + j] - M);
        Ssum += g_psl[s * BN + j];
    }
    float Sj = Ssum - (float)BN * M - (float)BN * logf(L + 1e-12f);
    float mc = (float)g_cnt[get_label(labels, j)];
    float w = mc / (mc + 1e-12f);
    double c = (double)(w * Sj);
#pragma unroll
    for (int o = 16; o >= 1; o >>= 1)
        c += __shfl_xor_sync(0xffffffffu, c, o);
    __shared__ double red[8];
    if ((threadIdx.x & 31) == 0) red[threadIdx.x >> 5] = c;
    __syncthreads();
    if (threadIdx.x < 8) {
        double v = red[threadIdx.x];
#pragma unroll
        for (int o = 4; o >= 1; o >>= 1)
            v += __shfl_xor_sync(0xffu, v, o);
        if (threadIdx.x == 0) atomicAdd(&g_acc, v);
    }
}

__global__ void k_final(float* out) {
    out[0] = (float)(-g_acc / ((double)BN * (double)BN));
}

// ---------------------------------------------------------------------------
extern "C" void kernel_launch(void* const* d_in, const int* in_sizes, int n_in,
                              void* d_out, int out_size) {
    const float* feats = (const float*)d_in[0];
    const void*  labels = d_in[1];
    const float* cov   = (const float*)d_in[2];
    float* out = (float*)d_out;

    cudaFuncSetAttribute(k_gemm_mma,
                         cudaFuncAttributeMaxDynamicSharedMemorySize, SMEM_BYTES);

    k_detect<<<1, 64>>>((const int*)labels);
    k_init<<<1, 128>>>();
    k_hist<<<BN / 256, 256>>>(labels);
    k_split<<<(BN * DD) / 256, 256>>>(feats);
    k_u<<<BN, DD>>>(feats, labels, cov);
    dim3 grid(BN / 128, NSPLIT);
    k_gemm_mma<<<grid, 256, SMEM_BYTES>>>();
    k_combine<<<BN / 256, 256>>>(labels);
    k_final<<<1, 1>>>(out);
}